// round 14
// baseline (speedup 1.0000x reference)
#include <cuda_runtime.h>
#include <cuda_fp16.h>
#include <cstdint>
#include <math.h>

#define BSZ    2
#define LSEQ   1024
#define DMODEL 512
#define DI     1024
#define NH     8
#define HDIM   128
#define DS     16
#define DTR    32
#define ODIM   560
#define ODIMP  640
#define MROWS  (BSZ*LSEQ)           // 2048
#define NCHUNK 16
#define CLEN   (LSEQ/NCHUNK)        // 64
#define NCHAN  (BSZ*NH*HDIM*DS)     // 32768
#define LOG2E  1.4426950408889634f

// ---------------- scratch (allocation-free: __device__ globals) ----------------
__device__ float g_xz[MROWS * 2 * DI];
__device__ float g_xc[MROWS * DI];
__device__ float g_proj[MROWS * ODIM];
__device__ float4 g_dx[MROWS * DI];        // {delta, xc, bd, gm}
__device__ float4 g_bc[MROWS * NH * DS];   // {Bre,Bim,Cre,Cim}
__device__ float2 g_ge[MROWS * NH];        // {sigmoid(lg), sigmoid(eg)}
__device__ float4 g_chA[NCHUNK][NCHAN];
__device__ float2 g_hin[NCHUNK][NCHAN];
// fp16 operands for tensor-core GEMMs
__device__ __half g_xh[MROWS*DMODEL];
__device__ __half g_w1h[2*DI*DMODEL];
__device__ __half g_xch[MROWS*DI];
__device__ __half g_w2h[ODIMP*DI];
__device__ __half g_ygh[MROWS*DI];
__device__ __half g_w3h[DMODEL*DI];

// ---------------- PTX helpers ----------------
__device__ __forceinline__ unsigned smem_u32(const void* p) {
    unsigned a;
    asm("{ .reg .u64 t; cvta.to.shared.u64 t, %1; cvt.u32.u64 %0, t; }" : "=r"(a) : "l"(p));
    return a;
}
#define CP16(dst,src)  asm volatile("cp.async.cg.shared.global [%0], [%1], 16;"::"r"(dst),"l"(src):"memory")
#define CP_COMMIT()    asm volatile("cp.async.commit_group;":::"memory")
#define CP_WAIT1()     asm volatile("cp.async.wait_group 1;":::"memory")
#define CP_WAIT0()     asm volatile("cp.async.wait_group 0;":::"memory")

#define LDMX4(r0,r1,r2,r3,addr) \
    asm volatile("ldmatrix.sync.aligned.m8n8.x4.shared.b16 {%0,%1,%2,%3}, [%4];" \
        : "=r"(r0),"=r"(r1),"=r"(r2),"=r"(r3) : "r"(addr))

__device__ __forceinline__ void mma16816(float* d, const unsigned* a, const unsigned* b) {
    asm volatile(
        "mma.sync.aligned.m16n8k16.row.col.f32.f16.f16.f32 "
        "{%0,%1,%2,%3}, {%4,%5,%6,%7}, {%8,%9}, {%0,%1,%2,%3};"
        : "+f"(d[0]), "+f"(d[1]), "+f"(d[2]), "+f"(d[3])
        : "r"(a[0]), "r"(a[1]), "r"(a[2]), "r"(a[3]), "r"(b[0]), "r"(b[1]));
}

// ---- fp16 HMMA GEMM, BK=64, 2-stage cp.async pipeline, optional split-K ----
template<int BM, int KSPLIT>
__global__ __launch_bounds__(256) void hmma_gemm(
    const __half* __restrict__ A, const __half* __restrict__ B,
    float* __restrict__ C, int ldc, int N, int K)
{
    constexpr int MT = BM / 32;
    constexpr int BUF = (BM + 128) * 144;
    extern __shared__ char smem[];
    const unsigned sbase = smem_u32(smem);
    const int tid = threadIdx.x, wid = tid >> 5, lane = tid & 31;
    const int m0 = blockIdx.y * BM, n0 = blockIdx.x * 128;
    const int wm = wid & 1, wn = wid >> 1;
    const int Ksub = K / KSPLIT;
    const int koff = blockIdx.z * Ksub;
    const int kc = Ksub >> 6;

    float acc[MT][4][4];
#pragma unroll
    for (int i = 0; i < MT; i++)
#pragma unroll
        for (int j = 0; j < 4; j++)
#pragma unroll
            for (int q = 0; q < 4; q++) acc[i][j][q] = 0.f;

    auto stage = [&](int c, int buf) {
        int kk = koff + c * 64;
        unsigned sa = sbase + buf * BUF;
        unsigned sb = sa + BM * 144;
#pragma unroll
        for (int i = tid; i < BM*8; i += 256) {
            int row = i >> 3, seg = i & 7;
            CP16(sa + row*144 + seg*16, A + (size_t)(m0 + row) * K + kk + seg*8);
        }
#pragma unroll
        for (int i = tid; i < 1024; i += 256) {
            int row = i >> 3, seg = i & 7;
            CP16(sb + row*144 + seg*16, B + (size_t)(n0 + row) * K + kk + seg*8);
        }
    };

    stage(0, 0); CP_COMMIT();
    for (int c = 0; c < kc; c++) {
        if (c + 1 < kc) { stage(c + 1, (c + 1) & 1); CP_COMMIT(); CP_WAIT1(); }
        else            { CP_WAIT0(); }
        __syncthreads();
        unsigned sa = sbase + (c & 1) * BUF;
        unsigned sb = sa + BM * 144;
#pragma unroll
        for (int ks = 0; ks < 4; ks++) {
            unsigned af[MT][4];
#pragma unroll
            for (int mt = 0; mt < MT; mt++) {
                int row = wm * (BM/2) + mt * 16 + (lane & 7) + ((lane >> 3) & 1) * 8;
                unsigned col = ((lane >> 4) * 16) + ks * 32;
                LDMX4(af[mt][0], af[mt][1], af[mt][2], af[mt][3], sa + row*144 + col);
            }
            unsigned bf[4][2];
#pragma unroll
            for (int ntp = 0; ntp < 2; ntp++) {
                int rowb = wn * 32 + ntp * 16 + (lane & 7) + ((lane >> 4) << 3);
                unsigned col = (((lane >> 3) & 1) * 16) + ks * 32;
                LDMX4(bf[2*ntp][0], bf[2*ntp][1], bf[2*ntp+1][0], bf[2*ntp+1][1],
                      sb + rowb*144 + col);
            }
#pragma unroll
            for (int mt = 0; mt < MT; mt++)
#pragma unroll
                for (int nt = 0; nt < 4; nt++)
                    mma16816(acc[mt][nt], af[mt], bf[nt]);
        }
        __syncthreads();
    }

#pragma unroll
    for (int mt = 0; mt < MT; mt++) {
#pragma unroll
        for (int nt = 0; nt < 4; nt++) {
            int row = m0 + wm * (BM/2) + mt * 16 + (lane >> 2);
            int col = n0 + wn * 32 + nt * 8 + (lane & 3) * 2;
            if (col < N) {
                if (KSPLIT > 1) {
                    atomicAdd(C + (size_t)row * ldc + col,     acc[mt][nt][0]);
                    atomicAdd(C + (size_t)row * ldc + col + 1, acc[mt][nt][1]);
                    atomicAdd(C + (size_t)(row+8) * ldc + col,     acc[mt][nt][2]);
                    atomicAdd(C + (size_t)(row+8) * ldc + col + 1, acc[mt][nt][3]);
                } else {
                    *(float2*)(C + (size_t)row * ldc + col) =
                        make_float2(acc[mt][nt][0], acc[mt][nt][1]);
                    *(float2*)(C + (size_t)(row + 8) * ldc + col) =
                        make_float2(acc[mt][nt][2], acc[mt][nt][3]);
                }
            }
        }
    }
}

// ------ fused fp32 -> fp16 converts + split-K output zeroing (1 launch) ------
#define SPN1 (MROWS*DMODEL)
#define SPN2 (2*DI*DMODEL)
#define SPN3 (ODIM*DI)
#define SPN3P (ODIMP*DI)
#define SPN4 (DMODEL*DI)
#define SPTOT (SPN1 + SPN2 + SPN3P + SPN4)
#define ZN1 (MROWS*ODIM)
#define ZN2 (MROWS*DMODEL)
#define ZTOT ((ZN1 + ZN2) / 4)
__global__ void split_all_kernel(const float* __restrict__ x,
                                 const float* __restrict__ w1,
                                 const float* __restrict__ w2,
                                 const float* __restrict__ w3,
                                 float* __restrict__ zp1,
                                 float* __restrict__ zp2)
{
    int i = blockIdx.x * 256 + threadIdx.x;
    if (i >= SPTOT) {
        int j = i - SPTOT;
        if (j < ZN1/4) *(float4*)(zp1 + j*4) = make_float4(0,0,0,0);
        else if (j < ZTOT) *(float4*)(zp2 + (j - ZN1/4)*4) = make_float4(0,0,0,0);
        return;
    }
    __half* dst; int idx; float v;
    if (i < SPN1) { idx = i; dst = g_xh; v = x[idx]; }
    else if (i < SPN1 + SPN2) { idx = i - SPN1; dst = g_w1h; v = w1[idx]; }
    else if (i < SPN1 + SPN2 + SPN3P) {
        idx = i - SPN1 - SPN2; dst = g_w2h;
        v = (idx < SPN3) ? w2[idx] : 0.f;
    }
    else {
        idx = i - SPN1 - SPN2 - SPN3P; dst = g_w3h; v = w3[idx];
    }
    dst[idx] = __float2half(v);
}

// ------ SIMT SGEMM (dtproj, K=32), softplus, packs {delta,xc,bd,gm} ---------
__global__ __launch_bounds__(256) void sgemm_sp(
    const float* __restrict__ A, int lda,
    const float* __restrict__ B, int ldb,
    const float* __restrict__ bias, int K)
{
    __shared__ float As[2][8][128];
    __shared__ float Bs[2][8][128];
    const int tid = threadIdx.x;
    const int m0 = blockIdx.y * 128, n0 = blockIdx.x * 128;
    const int tx = tid & 15, ty = tid >> 4;
    const int alr = tid >> 1, alk = (tid & 1) << 2;
    const float* Ap = A + (size_t)(m0 + alr) * lda + alk;
    const float* Bp = B + (size_t)(n0 + alr) * ldb + alk;

    float acc[8][8];
#pragma unroll
    for (int i = 0; i < 8; i++)
#pragma unroll
        for (int j = 0; j < 8; j++) acc[i][j] = 0.f;

    const int nk = K >> 3;
    float4 av = *(const float4*)Ap;
    float4 bv = *(const float4*)Bp;
    As[0][alk+0][alr]=av.x; As[0][alk+1][alr]=av.y; As[0][alk+2][alr]=av.z; As[0][alk+3][alr]=av.w;
    Bs[0][alk+0][alr]=bv.x; Bs[0][alk+1][alr]=bv.y; Bs[0][alk+2][alr]=bv.z; Bs[0][alk+3][alr]=bv.w;
    __syncthreads();
    int cur = 0;
    for (int kt = 0; kt < nk; kt++) {
        const bool more = (kt + 1) < nk;
        if (more) { av = *(const float4*)(Ap + (kt+1)*8); bv = *(const float4*)(Bp + (kt+1)*8); }
#pragma unroll
        for (int k = 0; k < 8; k++) {
            float4 a0 = *(const float4*)&As[cur][k][ty*8];
            float4 a1 = *(const float4*)&As[cur][k][ty*8+4];
            float4 b0 = *(const float4*)&Bs[cur][k][tx*8];
            float4 b1 = *(const float4*)&Bs[cur][k][tx*8+4];
            float a[8] = {a0.x,a0.y,a0.z,a0.w,a1.x,a1.y,a1.z,a1.w};
            float bb[8] = {b0.x,b0.y,b0.z,b0.w,b1.x,b1.y,b1.z,b1.w};
#pragma unroll
            for (int i = 0; i < 8; i++)
#pragma unroll
                for (int j = 0; j < 8; j++)
                    acc[i][j] = fmaf(a[i], bb[j], acc[i][j]);
        }
        if (more) {
            int nxt = cur ^ 1;
            As[nxt][alk+0][alr]=av.x; As[nxt][alk+1][alr]=av.y; As[nxt][alk+2][alr]=av.z; As[nxt][alk+3][alr]=av.w;
            Bs[nxt][alk+0][alr]=bv.x; Bs[nxt][alk+1][alr]=bv.y; Bs[nxt][alk+2][alr]=bv.z; Bs[nxt][alk+3][alr]=bv.w;
            __syncthreads();
            cur = nxt;
        }
    }
    int hcol = (n0 + tx * 8) >> 7;
#pragma unroll
    for (int i = 0; i < 8; i++) {
        int m = m0 + ty * 8 + i;
        float2 ge = g_ge[(size_t)m * NH + hcol];
        const float* xcrow = g_xc + (size_t)m * DI + n0 + tx * 8;
        float4* drow = g_dx + (size_t)m * DI + n0 + tx * 8;
#pragma unroll
        for (int j = 0; j < 8; j++) {
            float v = acc[i][j] + bias[n0 + tx*8 + j];
            v = (v > 20.f) ? v : log1pf(__expf(v));
            float bd = (1.f - ge.x) * v;
            float gm = ge.x * v * ge.y;
            drow[j] = make_float4(v, xcrow[j], bd, gm);
        }
    }
}

// ------- causal depthwise conv3 + bias + silu, float4 vectorized ------------
__global__ void conv_silu_kernel(const float* __restrict__ conv_w,
                                 const float* __restrict__ conv_b)
{
    int idx = blockIdx.x * 256 + threadIdx.x;
    if (idx >= MROWS * DI / 4) return;
    int c4  = (idx & (DI/4 - 1)) * 4;
    int row = idx / (DI/4);
    int l   = row % LSEQ;
    const float* col = g_xz + (size_t)row * (2*DI) + c4;
    float4 v2 = *(const float4*)col;
    float4 v1 = (l >= 1) ? *(const float4*)(col - 2*DI) : make_float4(0,0,0,0);
    float4 v0 = (l >= 2) ? *(const float4*)(col - 4*DI) : make_float4(0,0,0,0);
    float r[4];
#pragma unroll
    for (int j = 0; j < 4; j++) {
        int c = c4 + j;
        float s = conv_b[c]
                + ((const float*)&v2)[j] * conv_w[c*3+2]
                + ((const float*)&v1)[j] * conv_w[c*3+1]
                + ((const float*)&v0)[j] * conv_w[c*3+0];
        r[j] = s / (1.f + __expf(-s));
    }
    *(float4*)(g_xc + (size_t)row * DI + c4) = make_float4(r[0], r[1], r[2], r[3]);
    __half h[4];
#pragma unroll
    for (int j = 0; j < 4; j++) h[j] = __float2half(r[j]);
    *(uint2*)(g_xch + (size_t)row * DI + c4) = *(uint2*)h;
}

// ---------------- repack proj for the scan ----------------------------------
__global__ void repack_kernel()
{
    int i = blockIdx.x * 256 + threadIdx.x;
    if (i >= MROWS * NH * DS) return;
    int n = i & 15, h = (i >> 4) & 7, row = i >> 7;
    const float* pr = g_proj + (size_t)row * ODIM;
    int bcol = DTR + h * DS + n;
    g_bc[i] = make_float4(pr[bcol], pr[bcol+128], pr[bcol+256], pr[bcol+384]);
    if (n == 0) {
        float lg = 1.f / (1.f + __expf(-pr[544 + h]));
        float eg = 1.f / (1.f + __expf(-pr[552 + h]));
        g_ge[row * NH + h] = make_float2(lg, eg);
    }
}

// -------- scan core: h' = a*(h + bd*Bxp) + gm*Bx  (no clamp; see R9) --------
__device__ __forceinline__ void scan_step(
    float Are2, float Aim, float4 bc, float4 dx,
    float& Bxpr, float& Bxpi, float& hr, float& hi)
{
    float dlt = dx.x, xcv = dx.y, bd = dx.z, gm = dx.w;
    float er = exp2f(dlt * Are2);
    float sn, cs;
    __sincosf(dlt * Aim, &sn, &cs);
    float ar = er * cs, ai = er * sn;
    float Bxr = xcv * bc.x, Bxi = xcv * bc.y;
    float tr = fmaf(bd, Bxpr, hr);
    float ti = fmaf(bd, Bxpi, hi);
    hr = fmaf(gm, Bxr, ar*tr - ai*ti);
    hi = fmaf(gm, Bxi, ar*ti + ai*tr);
    Bxpr = Bxr; Bxpi = Bxi;
}

__global__ __launch_bounds__(256) void scan_partial(
    const float* __restrict__ A_log, const float* __restrict__ A_imag)
{
    int blk = blockIdx.x;
    int chunk = blk >> 7;
    int rest = blk & 127;
    int bh = rest >> 3, sub = rest & 7;
    int b = bh >> 3, h = bh & 7;
    int tid = threadIdx.x, warp = tid >> 5, lane = tid & 31;
    int n = lane & 15;
    int hd = sub*16 + warp*2 + (lane >> 4);

    float Are2 = -__expf(A_log[h*DS+n]) * LOG2E;
    float Aim = A_imag[h*DS+n];
    const int ccol = h*HDIM + hd;
    int l0 = chunk * CLEN;
    int row0 = b * LSEQ + l0;

    size_t bci = (size_t)row0 * (NH*DS) + h*DS + n;
    size_t dxi = (size_t)row0 * DI + ccol;

    float Bxpr = 0.f, Bxpi = 0.f;
    if (l0 > 0) {
        float4 bc0 = g_bc[bci - NH*DS];
        float4 dx0 = g_dx[dxi - DI];
        Bxpr = dx0.y * bc0.x; Bxpi = dx0.y * bc0.y;
    }
    float hr=0.f, hi=0.f, S=0.f;
    // software-pipelined: prefetch next step's operands before current compute
    float4 bc = g_bc[bci];
    float4 dx = g_dx[dxi];
#pragma unroll 4
    for (int l = 0; l < CLEN; l++) {
        float4 bcc = bc, dxc = dx;
        bci += NH*DS; dxi += DI;
        if (l + 1 < CLEN) { bc = g_bc[bci]; dx = g_dx[dxi]; }
        S += dxc.x;
        scan_step(Are2, Aim, bcc, dxc, Bxpr, Bxpi, hr, hi);
    }
    float er = exp2f(S * Are2);
    float sn, cs;
    __sincosf(S * Aim, &sn, &cs);
    int c = bh*2048 + sub*256 + tid;
    g_chA[chunk][c] = make_float4(er*cs, er*sn, hr, hi);
}

__global__ __launch_bounds__(256) void scan_combine()
{
    int c = blockIdx.x * 256 + threadIdx.x;
    float hr = 0.f, hi = 0.f;
#pragma unroll
    for (int ch = 0; ch < NCHUNK; ch++) {
        float4 v = g_chA[ch][c];
        g_hin[ch][c] = make_float2(hr, hi);
        float nr = v.x*hr - v.y*hi + v.z;
        float ni = v.x*hi + v.y*hr + v.w;
        hr = nr; hi = ni;
    }
}

__global__ __launch_bounds__(256) void scan_final(
    const float* __restrict__ A_log, const float* __restrict__ A_imag,
    const float* __restrict__ Dp)
{
    int blk = blockIdx.x;
    int chunk = blk >> 7;
    int rest = blk & 127;
    int bh = rest >> 3, sub = rest & 7;
    int b = bh >> 3, h = bh & 7;
    int tid = threadIdx.x, warp = tid >> 5, lane = tid & 31;
    int n = lane & 15;
    int hd = sub*16 + warp*2 + (lane >> 4);

    float Are2 = -__expf(A_log[h*DS+n]) * LOG2E;
    float Aim = A_imag[h*DS+n];
    float Dv  = Dp[h*HDIM + hd];
    const int ccol = h*HDIM + hd;
    int l0 = chunk * CLEN;
    int row0 = b * LSEQ + l0;
    const size_t zrow = (size_t)b * LSEQ * (2*DI);

    size_t bci = (size_t)row0 * (NH*DS) + h*DS + n;
    size_t dxi = (size_t)row0 * DI + ccol;

    float Bxpr = 0.f, Bxpi = 0.f;
    if (l0 > 0) {
        float4 bc0 = g_bc[bci - NH*DS];
        float4 dx0 = g_dx[dxi - DI];
        Bxpr = dx0.y * bc0.x; Bxpi = dx0.y * bc0.y;
    }
    int c = bh*2048 + sub*256 + tid;
    float2 h0 = g_hin[chunk][c];
    float hr = h0.x, hi = h0.y;

    float4 bc = g_bc[bci];
    float4 dx = g_dx[dxi];
#pragma unroll 4
    for (int l = l0; l < l0 + CLEN; l++) {
        float4 bcc = bc, dxc = dx;
        bci += NH*DS;
        if (l + 1 < l0 + CLEN) { bc = g_bc[bci]; dx = g_dx[dxi + DI]; }
        scan_step(Are2, Aim, bcc, dxc, Bxpr, Bxpi, hr, hi);

        float yv = hr*bcc.z + hi*bcc.w;
        yv += __shfl_xor_sync(0xffffffffu, yv, 1);
        yv += __shfl_xor_sync(0xffffffffu, yv, 2);
        yv += __shfl_xor_sync(0xffffffffu, yv, 4);
        yv += __shfl_xor_sync(0xffffffffu, yv, 8);

        if (n == 0) {
            float zv = g_xz[zrow + (size_t)l * (2*DI) + DI + ccol];
            float yt = yv + Dv * dxc.y;
            float sz = zv / (1.f + __expf(-zv));
            g_ygh[dxi] = __float2half(yt * sz);
        }
        dxi += DI;
    }
}

// ---------------- launch ----------------
extern "C" void kernel_launch(void* const* d_in, const int* in_sizes, int n_in,
                              void* d_out, int out_size)
{
    const float* x          = (const float*)d_in[0];
    const float* in_proj_w  = (const float*)d_in[1];
    const float* conv_w     = (const float*)d_in[2];
    const float* conv_b     = (const float*)d_in[3];
    const float* x_proj_w   = (const float*)d_in[4];
    const float* dt_proj_w  = (const float*)d_in[5];
    const float* dt_proj_b  = (const float*)d_in[6];
    const float* A_log      = (const float*)d_in[7];
    const float* A_imag     = (const float*)d_in[8];
    const float* Dp         = (const float*)d_in[9];
    const float* out_proj_w = (const float*)d_in[10];
    float* out = (float*)d_out;

    float *xz, *proj;
    cudaGetSymbolAddress((void**)&xz,   g_xz);
    cudaGetSymbolAddress((void**)&proj, g_proj);
    __half *xh, *w1h, *xch, *w2h, *ygh, *w3h;
    cudaGetSymbolAddress((void**)&xh,  g_xh);
    cudaGetSymbolAddress((void**)&w1h, g_w1h);
    cudaGetSymbolAddress((void**)&xch, g_xch);
    cudaGetSymbolAddress((void**)&w2h, g_w2h);
    cudaGetSymbolAddress((void**)&ygh, g_ygh);
    cudaGetSymbolAddress((void**)&w3h, g_w3h);

    const int smem64 = (64 + 128) * 144 * 2;   // 55296
    cudaFuncSetAttribute((void*)hmma_gemm<64,1>, cudaFuncAttributeMaxDynamicSharedMemorySize, smem64);
    cudaFuncSetAttribute((void*)hmma_gemm<64,2>, cudaFuncAttributeMaxDynamicSharedMemorySize, smem64);

    // 0) fp16 converts + zero split-K targets (proj, out)
    split_all_kernel<<<(SPTOT + ZTOT + 255)/256, 256>>>(x, in_proj_w, x_proj_w, out_proj_w,
                                                        proj, out);
    // 1) xz = x @ in_proj_w^T   (2048 x 2048, K=512) -> 512 blocks
    hmma_gemm<64,1><<<dim3(16,32), 256, smem64>>>(xh, w1h, xz, 2*DI, 2*DI, DMODEL);
    // 2) xc = silu(conv3(xp)+b)  (+ fp16 convert)
    conv_silu_kernel<<<(MROWS*DI/4 + 255)/256, 256>>>(conv_w, conv_b);
    // 3) proj = xc @ x_proj_w^T (2048 x 560, K=1024), split-K=2 -> 320 blocks
    hmma_gemm<64,2><<<dim3(ODIMP/128,32,2), 256, smem64>>>(xch, w2h, proj, ODIM, ODIM, DI);
    // 4a) repack B/C/gates (must precede sgemm_sp: it reads g_ge)
    repack_kernel<<<(MROWS*NH*DS + 255)/256, 256>>>();
    // 4b) delta = softplus(...) -> packs {delta, xc, bd, gm}
    sgemm_sp<<<dim3(8,16), 256>>>(proj, ODIM, dt_proj_w, DTR, dt_proj_b, DTR);
    // 5) chunked complex scan (software-pipelined)
    scan_partial<<<NCHUNK*128, 256>>>(A_log, A_imag);
    scan_combine<<<NCHAN/256, 256>>>();
    scan_final<<<NCHUNK*128, 256>>>(A_log, A_imag, Dp);
    // 6) out = yg @ out_proj_w^T (2048 x 512, K=1024), split-K=2 -> 256 blocks
    hmma_gemm<64,2><<<dim3(4,32,2), 256, smem64>>>(ygh, w3h, out, DMODEL, DMODEL, DI);
}

// round 15
// speedup vs baseline: 1.1233x; 1.1233x over previous
#include <cuda_runtime.h>
#include <cuda_fp16.h>
#include <cstdint>
#include <math.h>

#define BSZ    2
#define LSEQ   1024
#define DMODEL 512
#define DI     1024
#define NH     8
#define HDIM   128
#define DS     16
#define DTR    32
#define ODIM   560
#define ODIMP  640
#define MROWS  (BSZ*LSEQ)           // 2048
#define NCHUNK 16
#define CLEN   (LSEQ/NCHUNK)        // 64
#define NCHAN  (BSZ*NH*HDIM*DS)     // 32768
#define LOG2E  1.4426950408889634f

// ---------------- scratch (allocation-free: __device__ globals) ----------------
__device__ float g_xz[MROWS * 2 * DI];
__device__ float g_xc[MROWS * DI];
__device__ float g_proj[MROWS * ODIM];
__device__ float4 g_dx[MROWS * DI];        // {delta, xc, bd*xc_prev, gm*xc}
__device__ float4 g_bc[MROWS * NH * DS];   // {Bre,Bim,Cre,Cim}
__device__ float2 g_ge[MROWS * NH];        // {sigmoid(lg), sigmoid(eg)}
__device__ float4 g_chA[NCHUNK][NCHAN];
__device__ float2 g_hin[NCHUNK][NCHAN];
// fp16 operands for tensor-core GEMMs
__device__ __half g_xh[MROWS*DMODEL];
__device__ __half g_w1h[2*DI*DMODEL];
__device__ __half g_xch[MROWS*DI];
__device__ __half g_w2h[ODIMP*DI];
__device__ __half g_ygh[MROWS*DI];
__device__ __half g_w3h[DMODEL*DI];

// ---------------- PTX helpers ----------------
__device__ __forceinline__ unsigned smem_u32(const void* p) {
    unsigned a;
    asm("{ .reg .u64 t; cvta.to.shared.u64 t, %1; cvt.u32.u64 %0, t; }" : "=r"(a) : "l"(p));
    return a;
}
#define CP16(dst,src)  asm volatile("cp.async.cg.shared.global [%0], [%1], 16;"::"r"(dst),"l"(src):"memory")
#define CP_COMMIT()    asm volatile("cp.async.commit_group;":::"memory")
#define CP_WAIT1()     asm volatile("cp.async.wait_group 1;":::"memory")
#define CP_WAIT0()     asm volatile("cp.async.wait_group 0;":::"memory")

#define LDMX4(r0,r1,r2,r3,addr) \
    asm volatile("ldmatrix.sync.aligned.m8n8.x4.shared.b16 {%0,%1,%2,%3}, [%4];" \
        : "=r"(r0),"=r"(r1),"=r"(r2),"=r"(r3) : "r"(addr))

__device__ __forceinline__ void mma16816(float* d, const unsigned* a, const unsigned* b) {
    asm volatile(
        "mma.sync.aligned.m16n8k16.row.col.f32.f16.f16.f32 "
        "{%0,%1,%2,%3}, {%4,%5,%6,%7}, {%8,%9}, {%0,%1,%2,%3};"
        : "+f"(d[0]), "+f"(d[1]), "+f"(d[2]), "+f"(d[3])
        : "r"(a[0]), "r"(a[1]), "r"(a[2]), "r"(a[3]), "r"(b[0]), "r"(b[1]));
}

// ---- fp16 HMMA GEMM, BK=64, 2-stage cp.async pipeline, optional split-K ----
template<int BM, int KSPLIT>
__global__ __launch_bounds__(256) void hmma_gemm(
    const __half* __restrict__ A, const __half* __restrict__ B,
    float* __restrict__ C, int ldc, int N, int K)
{
    constexpr int MT = BM / 32;
    constexpr int BUF = (BM + 128) * 144;
    extern __shared__ char smem[];
    const unsigned sbase = smem_u32(smem);
    const int tid = threadIdx.x, wid = tid >> 5, lane = tid & 31;
    const int m0 = blockIdx.y * BM, n0 = blockIdx.x * 128;
    const int wm = wid & 1, wn = wid >> 1;
    const int Ksub = K / KSPLIT;
    const int koff = blockIdx.z * Ksub;
    const int kc = Ksub >> 6;

    float acc[MT][4][4];
#pragma unroll
    for (int i = 0; i < MT; i++)
#pragma unroll
        for (int j = 0; j < 4; j++)
#pragma unroll
            for (int q = 0; q < 4; q++) acc[i][j][q] = 0.f;

    auto stage = [&](int c, int buf) {
        int kk = koff + c * 64;
        unsigned sa = sbase + buf * BUF;
        unsigned sb = sa + BM * 144;
#pragma unroll
        for (int i = tid; i < BM*8; i += 256) {
            int row = i >> 3, seg = i & 7;
            CP16(sa + row*144 + seg*16, A + (size_t)(m0 + row) * K + kk + seg*8);
        }
#pragma unroll
        for (int i = tid; i < 1024; i += 256) {
            int row = i >> 3, seg = i & 7;
            CP16(sb + row*144 + seg*16, B + (size_t)(n0 + row) * K + kk + seg*8);
        }
    };

    stage(0, 0); CP_COMMIT();
    for (int c = 0; c < kc; c++) {
        if (c + 1 < kc) { stage(c + 1, (c + 1) & 1); CP_COMMIT(); CP_WAIT1(); }
        else            { CP_WAIT0(); }
        __syncthreads();
        unsigned sa = sbase + (c & 1) * BUF;
        unsigned sb = sa + BM * 144;
#pragma unroll
        for (int ks = 0; ks < 4; ks++) {
            unsigned af[MT][4];
#pragma unroll
            for (int mt = 0; mt < MT; mt++) {
                int row = wm * (BM/2) + mt * 16 + (lane & 7) + ((lane >> 3) & 1) * 8;
                unsigned col = ((lane >> 4) * 16) + ks * 32;
                LDMX4(af[mt][0], af[mt][1], af[mt][2], af[mt][3], sa + row*144 + col);
            }
            unsigned bf[4][2];
#pragma unroll
            for (int ntp = 0; ntp < 2; ntp++) {
                int rowb = wn * 32 + ntp * 16 + (lane & 7) + ((lane >> 4) << 3);
                unsigned col = (((lane >> 3) & 1) * 16) + ks * 32;
                LDMX4(bf[2*ntp][0], bf[2*ntp][1], bf[2*ntp+1][0], bf[2*ntp+1][1],
                      sb + rowb*144 + col);
            }
#pragma unroll
            for (int mt = 0; mt < MT; mt++)
#pragma unroll
                for (int nt = 0; nt < 4; nt++)
                    mma16816(acc[mt][nt], af[mt], bf[nt]);
        }
        __syncthreads();
    }

#pragma unroll
    for (int mt = 0; mt < MT; mt++) {
#pragma unroll
        for (int nt = 0; nt < 4; nt++) {
            int row = m0 + wm * (BM/2) + mt * 16 + (lane >> 2);
            int col = n0 + wn * 32 + nt * 8 + (lane & 3) * 2;
            if (col < N) {
                if (KSPLIT > 1) {
                    atomicAdd(C + (size_t)row * ldc + col,     acc[mt][nt][0]);
                    atomicAdd(C + (size_t)row * ldc + col + 1, acc[mt][nt][1]);
                    atomicAdd(C + (size_t)(row+8) * ldc + col,     acc[mt][nt][2]);
                    atomicAdd(C + (size_t)(row+8) * ldc + col + 1, acc[mt][nt][3]);
                } else {
                    *(float2*)(C + (size_t)row * ldc + col) =
                        make_float2(acc[mt][nt][0], acc[mt][nt][1]);
                    *(float2*)(C + (size_t)(row + 8) * ldc + col) =
                        make_float2(acc[mt][nt][2], acc[mt][nt][3]);
                }
            }
        }
    }
}

// ------ fused fp32 -> fp16 converts + split-K output zeroing (1 launch) ------
#define SPN1 (MROWS*DMODEL)
#define SPN2 (2*DI*DMODEL)
#define SPN3 (ODIM*DI)
#define SPN3P (ODIMP*DI)
#define SPN4 (DMODEL*DI)
#define SPTOT (SPN1 + SPN2 + SPN3P + SPN4)
#define ZN1 (MROWS*ODIM)
#define ZN2 (MROWS*DMODEL)
#define ZTOT ((ZN1 + ZN2) / 4)
__global__ void split_all_kernel(const float* __restrict__ x,
                                 const float* __restrict__ w1,
                                 const float* __restrict__ w2,
                                 const float* __restrict__ w3,
                                 float* __restrict__ zp1,
                                 float* __restrict__ zp2)
{
    int i = blockIdx.x * 256 + threadIdx.x;
    if (i >= SPTOT) {
        int j = i - SPTOT;
        if (j < ZN1/4) *(float4*)(zp1 + j*4) = make_float4(0,0,0,0);
        else if (j < ZTOT) *(float4*)(zp2 + (j - ZN1/4)*4) = make_float4(0,0,0,0);
        return;
    }
    __half* dst; int idx; float v;
    if (i < SPN1) { idx = i; dst = g_xh; v = x[idx]; }
    else if (i < SPN1 + SPN2) { idx = i - SPN1; dst = g_w1h; v = w1[idx]; }
    else if (i < SPN1 + SPN2 + SPN3P) {
        idx = i - SPN1 - SPN2; dst = g_w2h;
        v = (idx < SPN3) ? w2[idx] : 0.f;
    }
    else {
        idx = i - SPN1 - SPN2 - SPN3P; dst = g_w3h; v = w3[idx];
    }
    dst[idx] = __float2half(v);
}

// -- SIMT SGEMM (dtproj, K=32), softplus, packs {delta, xc, bd*xc_prev, gm*xc} --
__global__ __launch_bounds__(256) void sgemm_sp(
    const float* __restrict__ A, int lda,
    const float* __restrict__ B, int ldb,
    const float* __restrict__ bias, int K)
{
    __shared__ float As[2][8][128];
    __shared__ float Bs[2][8][128];
    const int tid = threadIdx.x;
    const int m0 = blockIdx.y * 128, n0 = blockIdx.x * 128;
    const int tx = tid & 15, ty = tid >> 4;
    const int alr = tid >> 1, alk = (tid & 1) << 2;
    const float* Ap = A + (size_t)(m0 + alr) * lda + alk;
    const float* Bp = B + (size_t)(n0 + alr) * ldb + alk;

    float acc[8][8];
#pragma unroll
    for (int i = 0; i < 8; i++)
#pragma unroll
        for (int j = 0; j < 8; j++) acc[i][j] = 0.f;

    const int nk = K >> 3;
    float4 av = *(const float4*)Ap;
    float4 bv = *(const float4*)Bp;
    As[0][alk+0][alr]=av.x; As[0][alk+1][alr]=av.y; As[0][alk+2][alr]=av.z; As[0][alk+3][alr]=av.w;
    Bs[0][alk+0][alr]=bv.x; Bs[0][alk+1][alr]=bv.y; Bs[0][alk+2][alr]=bv.z; Bs[0][alk+3][alr]=bv.w;
    __syncthreads();
    int cur = 0;
    for (int kt = 0; kt < nk; kt++) {
        const bool more = (kt + 1) < nk;
        if (more) { av = *(const float4*)(Ap + (kt+1)*8); bv = *(const float4*)(Bp + (kt+1)*8); }
#pragma unroll
        for (int k = 0; k < 8; k++) {
            float4 a0 = *(const float4*)&As[cur][k][ty*8];
            float4 a1 = *(const float4*)&As[cur][k][ty*8+4];
            float4 b0 = *(const float4*)&Bs[cur][k][tx*8];
            float4 b1 = *(const float4*)&Bs[cur][k][tx*8+4];
            float a[8] = {a0.x,a0.y,a0.z,a0.w,a1.x,a1.y,a1.z,a1.w};
            float bb[8] = {b0.x,b0.y,b0.z,b0.w,b1.x,b1.y,b1.z,b1.w};
#pragma unroll
            for (int i = 0; i < 8; i++)
#pragma unroll
                for (int j = 0; j < 8; j++)
                    acc[i][j] = fmaf(a[i], bb[j], acc[i][j]);
        }
        if (more) {
            int nxt = cur ^ 1;
            As[nxt][alk+0][alr]=av.x; As[nxt][alk+1][alr]=av.y; As[nxt][alk+2][alr]=av.z; As[nxt][alk+3][alr]=av.w;
            Bs[nxt][alk+0][alr]=bv.x; Bs[nxt][alk+1][alr]=bv.y; Bs[nxt][alk+2][alr]=bv.z; Bs[nxt][alk+3][alr]=bv.w;
            __syncthreads();
            cur = nxt;
        }
    }
    int hcol = (n0 + tx * 8) >> 7;
#pragma unroll
    for (int i = 0; i < 8; i++) {
        int m = m0 + ty * 8 + i;
        int l = m & (LSEQ - 1);
        float2 ge = g_ge[(size_t)m * NH + hcol];
        const float* xcrow  = g_xc + (size_t)m * DI + n0 + tx * 8;
        const float* xcprev = xcrow - DI;
        float4* drow = g_dx + (size_t)m * DI + n0 + tx * 8;
#pragma unroll
        for (int j = 0; j < 8; j++) {
            float v = acc[i][j] + bias[n0 + tx*8 + j];
            v = (v > 20.f) ? v : log1pf(__expf(v));
            float xcv = xcrow[j];
            float xcm1 = (l > 0) ? xcprev[j] : 0.f;
            float bd = (1.f - ge.x) * v;
            float gm = ge.x * v * ge.y;
            drow[j] = make_float4(v, xcv, bd * xcm1, gm * xcv);
        }
    }
}

// ------- causal depthwise conv3 + bias + silu, float4 vectorized ------------
__global__ void conv_silu_kernel(const float* __restrict__ conv_w,
                                 const float* __restrict__ conv_b)
{
    int idx = blockIdx.x * 256 + threadIdx.x;
    if (idx >= MROWS * DI / 4) return;
    int c4  = (idx & (DI/4 - 1)) * 4;
    int row = idx / (DI/4);
    int l   = row % LSEQ;
    const float* col = g_xz + (size_t)row * (2*DI) + c4;
    float4 v2 = *(const float4*)col;
    float4 v1 = (l >= 1) ? *(const float4*)(col - 2*DI) : make_float4(0,0,0,0);
    float4 v0 = (l >= 2) ? *(const float4*)(col - 4*DI) : make_float4(0,0,0,0);
    float r[4];
#pragma unroll
    for (int j = 0; j < 4; j++) {
        int c = c4 + j;
        float s = conv_b[c]
                + ((const float*)&v2)[j] * conv_w[c*3+2]
                + ((const float*)&v1)[j] * conv_w[c*3+1]
                + ((const float*)&v0)[j] * conv_w[c*3+0];
        r[j] = s / (1.f + __expf(-s));
    }
    *(float4*)(g_xc + (size_t)row * DI + c4) = make_float4(r[0], r[1], r[2], r[3]);
    __half h[4];
#pragma unroll
    for (int j = 0; j < 4; j++) h[j] = __float2half(r[j]);
    *(uint2*)(g_xch + (size_t)row * DI + c4) = *(uint2*)h;
}

// ---------------- repack proj for the scan ----------------------------------
__global__ void repack_kernel()
{
    int i = blockIdx.x * 256 + threadIdx.x;
    if (i >= MROWS * NH * DS) return;
    int n = i & 15, h = (i >> 4) & 7, row = i >> 7;
    const float* pr = g_proj + (size_t)row * ODIM;
    int bcol = DTR + h * DS + n;
    g_bc[i] = make_float4(pr[bcol], pr[bcol+128], pr[bcol+256], pr[bcol+384]);
    if (n == 0) {
        float lg = 1.f / (1.f + __expf(-pr[544 + h]));
        float eg = 1.f / (1.f + __expf(-pr[552 + h]));
        g_ge[row * NH + h] = make_float2(lg, eg);
    }
}

// ---- scan core: h' = a*(h + bdxp*Bp) + gmxc*B ; Bp = raw B_{l-1} state ----
// dx = {delta, xc, bd*xc_prev, gm*xc}; 12 FMA-pipe ops + 3 MUFU per step.
__device__ __forceinline__ void scan_step(
    float Are2, float Aim, float4 bc, float4 dx,
    float& Bpr, float& Bpi, float& hr, float& hi)
{
    float er = exp2f(dx.x * Are2);
    float sn, cs;
    __sincosf(dx.x * Aim, &sn, &cs);
    float ar = er * cs, ai = er * sn;
    float tr = fmaf(dx.z, Bpr, hr);
    float ti = fmaf(dx.z, Bpi, hi);
    hr = fmaf(dx.w, bc.x, ar*tr - ai*ti);
    hi = fmaf(dx.w, bc.y, ar*ti + ai*tr);
    Bpr = bc.x; Bpi = bc.y;
}

__global__ __launch_bounds__(256) void scan_partial(
    const float* __restrict__ A_log, const float* __restrict__ A_imag)
{
    int blk = blockIdx.x;
    int chunk = blk >> 7;
    int rest = blk & 127;
    int bh = rest >> 3, sub = rest & 7;
    int b = bh >> 3, h = bh & 7;
    int tid = threadIdx.x, warp = tid >> 5, lane = tid & 31;
    int n = lane & 15;
    int hd = sub*16 + warp*2 + (lane >> 4);

    float Are2 = -__expf(A_log[h*DS+n]) * LOG2E;
    float Aim = A_imag[h*DS+n];
    const int ccol = h*HDIM + hd;
    int l0 = chunk * CLEN;
    int row0 = b * LSEQ + l0;

    size_t bci = (size_t)row0 * (NH*DS) + h*DS + n;
    size_t dxi = (size_t)row0 * DI + ccol;

    float Bpr = 0.f, Bpi = 0.f;
    if (l0 > 0) {
        float4 bc0 = g_bc[bci - NH*DS];
        Bpr = bc0.x; Bpi = bc0.y;
    }
    float hr=0.f, hi=0.f, S=0.f;
    for (int l = 0; l < CLEN; l++) {
        float4 bc = g_bc[bci]; bci += NH*DS;
        float4 dx = g_dx[dxi]; dxi += DI;
        S += dx.x;
        scan_step(Are2, Aim, bc, dx, Bpr, Bpi, hr, hi);
    }
    float er = exp2f(S * Are2);
    float sn, cs;
    __sincosf(S * Aim, &sn, &cs);
    int c = bh*2048 + sub*256 + tid;
    g_chA[chunk][c] = make_float4(er*cs, er*sn, hr, hi);
}

__global__ __launch_bounds__(256) void scan_combine()
{
    int c = blockIdx.x * 256 + threadIdx.x;
    float hr = 0.f, hi = 0.f;
#pragma unroll
    for (int ch = 0; ch < NCHUNK; ch++) {
        float4 v = g_chA[ch][c];
        g_hin[ch][c] = make_float2(hr, hi);
        float nr = v.x*hr - v.y*hi + v.z;
        float ni = v.x*hi + v.y*hr + v.w;
        hr = nr; hi = ni;
    }
}

__global__ __launch_bounds__(256) void scan_final(
    const float* __restrict__ A_log, const float* __restrict__ A_imag,
    const float* __restrict__ Dp)
{
    int blk = blockIdx.x;
    int chunk = blk >> 7;
    int rest = blk & 127;
    int bh = rest >> 3, sub = rest & 7;
    int b = bh >> 3, h = bh & 7;
    int tid = threadIdx.x, warp = tid >> 5, lane = tid & 31;
    int n = lane & 15;
    int hd = sub*16 + warp*2 + (lane >> 4);

    float Are2 = -__expf(A_log[h*DS+n]) * LOG2E;
    float Aim = A_imag[h*DS+n];
    float Dv  = Dp[h*HDIM + hd];
    const int ccol = h*HDIM + hd;
    int l0 = chunk * CLEN;
    int row0 = b * LSEQ + l0;
    const size_t zrow = (size_t)b * LSEQ * (2*DI);

    size_t bci = (size_t)row0 * (NH*DS) + h*DS + n;
    size_t dxi = (size_t)row0 * DI + ccol;

    float Bpr = 0.f, Bpi = 0.f;
    if (l0 > 0) {
        float4 bc0 = g_bc[bci - NH*DS];
        Bpr = bc0.x; Bpi = bc0.y;
    }
    int c = bh*2048 + sub*256 + tid;
    float2 h0 = g_hin[chunk][c];
    float hr = h0.x, hi = h0.y;

    for (int l = l0; l < l0 + CLEN; l++) {
        float4 bc = g_bc[bci]; bci += NH*DS;
        float4 dx = g_dx[dxi];
        scan_step(Are2, Aim, bc, dx, Bpr, Bpi, hr, hi);

        float yv = hr*bc.z + hi*bc.w;
        yv += __shfl_xor_sync(0xffffffffu, yv, 1);
        yv += __shfl_xor_sync(0xffffffffu, yv, 2);
        yv += __shfl_xor_sync(0xffffffffu, yv, 4);
        yv += __shfl_xor_sync(0xffffffffu, yv, 8);

        if (n == 0) {
            float zv = g_xz[zrow + (size_t)l * (2*DI) + DI + ccol];
            float yt = yv + Dv * dx.y;
            float sz = zv / (1.f + __expf(-zv));
            g_ygh[dxi] = __float2half(yt * sz);
        }
        dxi += DI;
    }
}

// ---------------- launch ----------------
extern "C" void kernel_launch(void* const* d_in, const int* in_sizes, int n_in,
                              void* d_out, int out_size)
{
    const float* x          = (const float*)d_in[0];
    const float* in_proj_w  = (const float*)d_in[1];
    const float* conv_w     = (const float*)d_in[2];
    const float* conv_b     = (const float*)d_in[3];
    const float* x_proj_w   = (const float*)d_in[4];
    const float* dt_proj_w  = (const float*)d_in[5];
    const float* dt_proj_b  = (const float*)d_in[6];
    const float* A_log      = (const float*)d_in[7];
    const float* A_imag     = (const float*)d_in[8];
    const float* Dp         = (const float*)d_in[9];
    const float* out_proj_w = (const float*)d_in[10];
    float* out = (float*)d_out;

    float *xz, *proj;
    cudaGetSymbolAddress((void**)&xz,   g_xz);
    cudaGetSymbolAddress((void**)&proj, g_proj);
    __half *xh, *w1h, *xch, *w2h, *ygh, *w3h;
    cudaGetSymbolAddress((void**)&xh,  g_xh);
    cudaGetSymbolAddress((void**)&w1h, g_w1h);
    cudaGetSymbolAddress((void**)&xch, g_xch);
    cudaGetSymbolAddress((void**)&w2h, g_w2h);
    cudaGetSymbolAddress((void**)&ygh, g_ygh);
    cudaGetSymbolAddress((void**)&w3h, g_w3h);

    const int smem64 = (64 + 128) * 144 * 2;   // 55296
    cudaFuncSetAttribute((void*)hmma_gemm<64,1>, cudaFuncAttributeMaxDynamicSharedMemorySize, smem64);
    cudaFuncSetAttribute((void*)hmma_gemm<64,2>, cudaFuncAttributeMaxDynamicSharedMemorySize, smem64);

    // 0) fp16 converts + zero split-K targets (proj, out)
    split_all_kernel<<<(SPTOT + ZTOT + 255)/256, 256>>>(x, in_proj_w, x_proj_w, out_proj_w,
                                                        proj, out);
    // 1) xz = x @ in_proj_w^T   (2048 x 2048, K=512) -> 512 blocks
    hmma_gemm<64,1><<<dim3(16,32), 256, smem64>>>(xh, w1h, xz, 2*DI, 2*DI, DMODEL);
    // 2) xc = silu(conv3(xp)+b)  (+ fp16 convert)
    conv_silu_kernel<<<(MROWS*DI/4 + 255)/256, 256>>>(conv_w, conv_b);
    // 3) proj = xc @ x_proj_w^T (2048 x 560, K=1024), split-K=2 -> 320 blocks
    hmma_gemm<64,2><<<dim3(ODIMP/128,32,2), 256, smem64>>>(xch, w2h, proj, ODIM, ODIM, DI);
    // 4a) repack B/C/gates (must precede sgemm_sp: it reads g_ge)
    repack_kernel<<<(MROWS*NH*DS + 255)/256, 256>>>();
    // 4b) delta = softplus(...) -> packs {delta, xc, bd*xc_prev, gm*xc}
    sgemm_sp<<<dim3(8,16), 256>>>(proj, ODIM, dt_proj_w, DTR, dt_proj_b, DTR);
    // 5) chunked complex scan (12-FMA step)
    scan_partial<<<NCHUNK*128, 256>>>(A_log, A_imag);
    scan_combine<<<NCHAN/256, 256>>>();
    scan_final<<<NCHUNK*128, 256>>>(A_log, A_imag, Dp);
    // 6) out = yg @ out_proj_w^T (2048 x 512, K=1024), split-K=2 -> 256 blocks
    hmma_gemm<64,2><<<dim3(4,32,2), 256, smem64>>>(ygh, w3h, out, DMODEL, DMODEL, DI);
}

// round 16
// speedup vs baseline: 1.1849x; 1.0548x over previous
#include <cuda_runtime.h>
#include <cuda_fp16.h>
#include <cstdint>
#include <math.h>

#define BSZ    2
#define LSEQ   1024
#define DMODEL 512
#define DI     1024
#define NH     8
#define HDIM   128
#define DS     16
#define DTR    32
#define ODIM   560
#define ODIMP  640
#define MROWS  (BSZ*LSEQ)           // 2048
#define NCHUNK 16
#define CLEN   (LSEQ/NCHUNK)        // 64
#define NCHAN  (BSZ*NH*HDIM*DS)     // 32768
#define LOG2E  1.4426950408889634f

// ---------------- scratch (allocation-free: __device__ globals) ----------------
__device__ float g_xz[MROWS * 2 * DI];
__device__ float g_xc[MROWS * DI];
__device__ float g_proj[MROWS * ODIM];
__device__ float4 g_dx[MROWS * DI];        // {delta, xc, bd, gm}
__device__ float4 g_bc[MROWS * NH * DS];   // {Bre,Bim,Cre,Cim}
__device__ float2 g_ge[MROWS * NH];        // {sigmoid(lg), sigmoid(eg)}
__device__ float4 g_chA[NCHUNK][NCHAN];
__device__ float2 g_hin[NCHUNK][NCHAN];
// fp16 operands for tensor-core GEMMs
__device__ __half g_xh[MROWS*DMODEL];
__device__ __half g_w1h[2*DI*DMODEL];
__device__ __half g_xch[MROWS*DI];
__device__ __half g_w2h[ODIMP*DI];
__device__ __half g_ygh[MROWS*DI];
__device__ __half g_w3h[DMODEL*DI];

// ---------------- PTX helpers ----------------
__device__ __forceinline__ unsigned smem_u32(const void* p) {
    unsigned a;
    asm("{ .reg .u64 t; cvta.to.shared.u64 t, %1; cvt.u32.u64 %0, t; }" : "=r"(a) : "l"(p));
    return a;
}
#define CP16(dst,src)  asm volatile("cp.async.cg.shared.global [%0], [%1], 16;"::"r"(dst),"l"(src):"memory")
#define CP_COMMIT()    asm volatile("cp.async.commit_group;":::"memory")
#define CP_WAIT1()     asm volatile("cp.async.wait_group 1;":::"memory")
#define CP_WAIT0()     asm volatile("cp.async.wait_group 0;":::"memory")

#define LDMX4(r0,r1,r2,r3,addr) \
    asm volatile("ldmatrix.sync.aligned.m8n8.x4.shared.b16 {%0,%1,%2,%3}, [%4];" \
        : "=r"(r0),"=r"(r1),"=r"(r2),"=r"(r3) : "r"(addr))

__device__ __forceinline__ void mma16816(float* d, const unsigned* a, const unsigned* b) {
    asm volatile(
        "mma.sync.aligned.m16n8k16.row.col.f32.f16.f16.f32 "
        "{%0,%1,%2,%3}, {%4,%5,%6,%7}, {%8,%9}, {%0,%1,%2,%3};"
        : "+f"(d[0]), "+f"(d[1]), "+f"(d[2]), "+f"(d[3])
        : "r"(a[0]), "r"(a[1]), "r"(a[2]), "r"(a[3]), "r"(b[0]), "r"(b[1]));
}

// ---- fp16 HMMA GEMM, BK=64, 2-stage cp.async pipeline, optional split-K ----
// BM x 128 tile, 8 warps (2m x 4n), warp tile (BM/2) x 32.
template<int BM, int KSPLIT>
__global__ __launch_bounds__(256) void hmma_gemm(
    const __half* __restrict__ A, const __half* __restrict__ B,
    float* __restrict__ C, int ldc, int N, int K)
{
    constexpr int MT = BM / 32;
    constexpr int BUF = (BM + 128) * 144;
    extern __shared__ char smem[];
    const unsigned sbase = smem_u32(smem);
    const int tid = threadIdx.x, wid = tid >> 5, lane = tid & 31;
    const int m0 = blockIdx.y * BM, n0 = blockIdx.x * 128;
    const int wm = wid & 1, wn = wid >> 1;
    const int Ksub = K / KSPLIT;
    const int koff = blockIdx.z * Ksub;
    const int kc = Ksub >> 6;

    float acc[MT][4][4];
#pragma unroll
    for (int i = 0; i < MT; i++)
#pragma unroll
        for (int j = 0; j < 4; j++)
#pragma unroll
            for (int q = 0; q < 4; q++) acc[i][j][q] = 0.f;

    auto stage = [&](int c, int buf) {
        int kk = koff + c * 64;
        unsigned sa = sbase + buf * BUF;
        unsigned sb = sa + BM * 144;
#pragma unroll
        for (int i = tid; i < BM*8; i += 256) {
            int row = i >> 3, seg = i & 7;
            CP16(sa + row*144 + seg*16, A + (size_t)(m0 + row) * K + kk + seg*8);
        }
#pragma unroll
        for (int i = tid; i < 1024; i += 256) {
            int row = i >> 3, seg = i & 7;
            CP16(sb + row*144 + seg*16, B + (size_t)(n0 + row) * K + kk + seg*8);
        }
    };

    stage(0, 0); CP_COMMIT();
    for (int c = 0; c < kc; c++) {
        if (c + 1 < kc) { stage(c + 1, (c + 1) & 1); CP_COMMIT(); CP_WAIT1(); }
        else            { CP_WAIT0(); }
        __syncthreads();
        unsigned sa = sbase + (c & 1) * BUF;
        unsigned sb = sa + BM * 144;
#pragma unroll
        for (int ks = 0; ks < 4; ks++) {
            unsigned af[MT][4];
#pragma unroll
            for (int mt = 0; mt < MT; mt++) {
                int row = wm * (BM/2) + mt * 16 + (lane & 7) + ((lane >> 3) & 1) * 8;
                unsigned col = ((lane >> 4) * 16) + ks * 32;
                LDMX4(af[mt][0], af[mt][1], af[mt][2], af[mt][3], sa + row*144 + col);
            }
            unsigned bf[4][2];
#pragma unroll
            for (int ntp = 0; ntp < 2; ntp++) {
                int rowb = wn * 32 + ntp * 16 + (lane & 7) + ((lane >> 4) << 3);
                unsigned col = (((lane >> 3) & 1) * 16) + ks * 32;
                LDMX4(bf[2*ntp][0], bf[2*ntp][1], bf[2*ntp+1][0], bf[2*ntp+1][1],
                      sb + rowb*144 + col);
            }
#pragma unroll
            for (int mt = 0; mt < MT; mt++)
#pragma unroll
                for (int nt = 0; nt < 4; nt++)
                    mma16816(acc[mt][nt], af[mt], bf[nt]);
        }
        __syncthreads();
    }

#pragma unroll
    for (int mt = 0; mt < MT; mt++) {
#pragma unroll
        for (int nt = 0; nt < 4; nt++) {
            int row = m0 + wm * (BM/2) + mt * 16 + (lane >> 2);
            int col = n0 + wn * 32 + nt * 8 + (lane & 3) * 2;
            if (col < N) {
                if (KSPLIT > 1) {
                    atomicAdd(C + (size_t)row * ldc + col,     acc[mt][nt][0]);
                    atomicAdd(C + (size_t)row * ldc + col + 1, acc[mt][nt][1]);
                    atomicAdd(C + (size_t)(row+8) * ldc + col,     acc[mt][nt][2]);
                    atomicAdd(C + (size_t)(row+8) * ldc + col + 1, acc[mt][nt][3]);
                } else {
                    *(float2*)(C + (size_t)row * ldc + col) =
                        make_float2(acc[mt][nt][0], acc[mt][nt][1]);
                    *(float2*)(C + (size_t)(row + 8) * ldc + col) =
                        make_float2(acc[mt][nt][2], acc[mt][nt][3]);
                }
            }
        }
    }
}

// ------ fused fp32 -> fp16 converts + split-K output zeroing (1 launch) ------
#define SPN1 (MROWS*DMODEL)
#define SPN2 (2*DI*DMODEL)
#define SPN3 (ODIM*DI)
#define SPN3P (ODIMP*DI)
#define SPN4 (DMODEL*DI)
#define SPTOT (SPN1 + SPN2 + SPN3P + SPN4)
#define ZN1 (MROWS*ODIM)
#define ZN2 (MROWS*DMODEL)
#define ZTOT ((ZN1 + ZN2) / 4)
__global__ void split_all_kernel(const float* __restrict__ x,
                                 const float* __restrict__ w1,
                                 const float* __restrict__ w2,
                                 const float* __restrict__ w3,
                                 float* __restrict__ zp1,
                                 float* __restrict__ zp2)
{
    int i = blockIdx.x * 256 + threadIdx.x;
    if (i >= SPTOT) {
        int j = i - SPTOT;
        if (j < ZN1/4) *(float4*)(zp1 + j*4) = make_float4(0,0,0,0);
        else if (j < ZTOT) *(float4*)(zp2 + (j - ZN1/4)*4) = make_float4(0,0,0,0);
        return;
    }
    __half* dst; int idx; float v;
    if (i < SPN1) { idx = i; dst = g_xh; v = x[idx]; }
    else if (i < SPN1 + SPN2) { idx = i - SPN1; dst = g_w1h; v = w1[idx]; }
    else if (i < SPN1 + SPN2 + SPN3P) {
        idx = i - SPN1 - SPN2; dst = g_w2h;
        v = (idx < SPN3) ? w2[idx] : 0.f;
    }
    else {
        idx = i - SPN1 - SPN2 - SPN3P; dst = g_w3h; v = w3[idx];
    }
    dst[idx] = __float2half(v);
}

// ------ SIMT SGEMM (dtproj, K=32), softplus, packs {delta,xc,bd,gm} ---------
__global__ __launch_bounds__(256) void sgemm_sp(
    const float* __restrict__ A, int lda,
    const float* __restrict__ B, int ldb,
    const float* __restrict__ bias, int K)
{
    __shared__ float As[2][8][128];
    __shared__ float Bs[2][8][128];
    const int tid = threadIdx.x;
    const int m0 = blockIdx.y * 128, n0 = blockIdx.x * 128;
    const int tx = tid & 15, ty = tid >> 4;
    const int alr = tid >> 1, alk = (tid & 1) << 2;
    const float* Ap = A + (size_t)(m0 + alr) * lda + alk;
    const float* Bp = B + (size_t)(n0 + alr) * ldb + alk;

    float acc[8][8];
#pragma unroll
    for (int i = 0; i < 8; i++)
#pragma unroll
        for (int j = 0; j < 8; j++) acc[i][j] = 0.f;

    const int nk = K >> 3;
    float4 av = *(const float4*)Ap;
    float4 bv = *(const float4*)Bp;
    As[0][alk+0][alr]=av.x; As[0][alk+1][alr]=av.y; As[0][alk+2][alr]=av.z; As[0][alk+3][alr]=av.w;
    Bs[0][alk+0][alr]=bv.x; Bs[0][alk+1][alr]=bv.y; Bs[0][alk+2][alr]=bv.z; Bs[0][alk+3][alr]=bv.w;
    __syncthreads();
    int cur = 0;
    for (int kt = 0; kt < nk; kt++) {
        const bool more = (kt + 1) < nk;
        if (more) { av = *(const float4*)(Ap + (kt+1)*8); bv = *(const float4*)(Bp + (kt+1)*8); }
#pragma unroll
        for (int k = 0; k < 8; k++) {
            float4 a0 = *(const float4*)&As[cur][k][ty*8];
            float4 a1 = *(const float4*)&As[cur][k][ty*8+4];
            float4 b0 = *(const float4*)&Bs[cur][k][tx*8];
            float4 b1 = *(const float4*)&Bs[cur][k][tx*8+4];
            float a[8] = {a0.x,a0.y,a0.z,a0.w,a1.x,a1.y,a1.z,a1.w};
            float bb[8] = {b0.x,b0.y,b0.z,b0.w,b1.x,b1.y,b1.z,b1.w};
#pragma unroll
            for (int i = 0; i < 8; i++)
#pragma unroll
                for (int j = 0; j < 8; j++)
                    acc[i][j] = fmaf(a[i], bb[j], acc[i][j]);
        }
        if (more) {
            int nxt = cur ^ 1;
            As[nxt][alk+0][alr]=av.x; As[nxt][alk+1][alr]=av.y; As[nxt][alk+2][alr]=av.z; As[nxt][alk+3][alr]=av.w;
            Bs[nxt][alk+0][alr]=bv.x; Bs[nxt][alk+1][alr]=bv.y; Bs[nxt][alk+2][alr]=bv.z; Bs[nxt][alk+3][alr]=bv.w;
            __syncthreads();
            cur = nxt;
        }
    }
    int hcol = (n0 + tx * 8) >> 7;
#pragma unroll
    for (int i = 0; i < 8; i++) {
        int m = m0 + ty * 8 + i;
        float2 ge = g_ge[(size_t)m * NH + hcol];
        const float* xcrow = g_xc + (size_t)m * DI + n0 + tx * 8;
        float4* drow = g_dx + (size_t)m * DI + n0 + tx * 8;
#pragma unroll
        for (int j = 0; j < 8; j++) {
            float v = acc[i][j] + bias[n0 + tx*8 + j];
            v = (v > 20.f) ? v : log1pf(__expf(v));
            float bd = (1.f - ge.x) * v;
            float gm = ge.x * v * ge.y;
            drow[j] = make_float4(v, xcrow[j], bd, gm);
        }
    }
}

// ------- causal depthwise conv3 + bias + silu, float4 vectorized ------------
__global__ void conv_silu_kernel(const float* __restrict__ conv_w,
                                 const float* __restrict__ conv_b)
{
    int idx = blockIdx.x * 256 + threadIdx.x;
    if (idx >= MROWS * DI / 4) return;
    int c4  = (idx & (DI/4 - 1)) * 4;
    int row = idx / (DI/4);
    int l   = row % LSEQ;
    const float* col = g_xz + (size_t)row * (2*DI) + c4;
    float4 v2 = *(const float4*)col;
    float4 v1 = (l >= 1) ? *(const float4*)(col - 2*DI) : make_float4(0,0,0,0);
    float4 v0 = (l >= 2) ? *(const float4*)(col - 4*DI) : make_float4(0,0,0,0);
    float r[4];
#pragma unroll
    for (int j = 0; j < 4; j++) {
        int c = c4 + j;
        float s = conv_b[c]
                + ((const float*)&v2)[j] * conv_w[c*3+2]
                + ((const float*)&v1)[j] * conv_w[c*3+1]
                + ((const float*)&v0)[j] * conv_w[c*3+0];
        r[j] = s / (1.f + __expf(-s));
    }
    *(float4*)(g_xc + (size_t)row * DI + c4) = make_float4(r[0], r[1], r[2], r[3]);
    __half h[4];
#pragma unroll
    for (int j = 0; j < 4; j++) h[j] = __float2half(r[j]);
    *(uint2*)(g_xch + (size_t)row * DI + c4) = *(uint2*)h;
}

// ---------------- repack proj for the scan ----------------------------------
__global__ void repack_kernel()
{
    int i = blockIdx.x * 256 + threadIdx.x;
    if (i >= MROWS * NH * DS) return;
    int n = i & 15, h = (i >> 4) & 7, row = i >> 7;
    const float* pr = g_proj + (size_t)row * ODIM;
    int bcol = DTR + h * DS + n;
    g_bc[i] = make_float4(pr[bcol], pr[bcol+128], pr[bcol+256], pr[bcol+384]);
    if (n == 0) {
        float lg = 1.f / (1.f + __expf(-pr[544 + h]));
        float eg = 1.f / (1.f + __expf(-pr[552 + h]));
        g_ge[row * NH + h] = make_float2(lg, eg);
    }
}

// -------- scan core (R13): h' = a*(h + bd*Bxp) + gm*Bx  (no clamp) ----------
__device__ __forceinline__ void scan_step(
    float Are2, float Aim, float4 bc, float4 dx,
    float& Bxpr, float& Bxpi, float& hr, float& hi)
{
    float dlt = dx.x, xcv = dx.y, bd = dx.z, gm = dx.w;
    float er = exp2f(dlt * Are2);
    float sn, cs;
    __sincosf(dlt * Aim, &sn, &cs);
    float ar = er * cs, ai = er * sn;
    float Bxr = xcv * bc.x, Bxi = xcv * bc.y;
    float tr = fmaf(bd, Bxpr, hr);
    float ti = fmaf(bd, Bxpi, hi);
    hr = fmaf(gm, Bxr, ar*tr - ai*ti);
    hi = fmaf(gm, Bxi, ar*ti + ai*tr);
    Bxpr = Bxr; Bxpi = Bxi;
}

__global__ __launch_bounds__(256) void scan_partial(
    const float* __restrict__ A_log, const float* __restrict__ A_imag)
{
    int blk = blockIdx.x;
    int chunk = blk >> 7;
    int rest = blk & 127;
    int bh = rest >> 3, sub = rest & 7;
    int b = bh >> 3, h = bh & 7;
    int tid = threadIdx.x, warp = tid >> 5, lane = tid & 31;
    int n = lane & 15;
    int hd = sub*16 + warp*2 + (lane >> 4);

    float Are2 = -__expf(A_log[h*DS+n]) * LOG2E;
    float Aim = A_imag[h*DS+n];
    const int ccol = h*HDIM + hd;
    int l0 = chunk * CLEN;
    int row0 = b * LSEQ + l0;

    size_t bci = (size_t)row0 * (NH*DS) + h*DS + n;
    size_t dxi = (size_t)row0 * DI + ccol;

    float Bxpr = 0.f, Bxpi = 0.f;
    if (l0 > 0) {
        float4 bc0 = g_bc[bci - NH*DS];
        float4 dx0 = g_dx[dxi - DI];
        Bxpr = dx0.y * bc0.x; Bxpi = dx0.y * bc0.y;
    }
    float hr=0.f, hi=0.f, S=0.f;
    for (int l = 0; l < CLEN; l++) {
        float4 bc = g_bc[bci]; bci += NH*DS;
        float4 dx = g_dx[dxi]; dxi += DI;
        S += dx.x;
        scan_step(Are2, Aim, bc, dx, Bxpr, Bxpi, hr, hi);
    }
    float er = exp2f(S * Are2);
    float sn, cs;
    __sincosf(S * Aim, &sn, &cs);
    int c = bh*2048 + sub*256 + tid;
    g_chA[chunk][c] = make_float4(er*cs, er*sn, hr, hi);
}

__global__ __launch_bounds__(256) void scan_combine()
{
    int c = blockIdx.x * 256 + threadIdx.x;
    float hr = 0.f, hi = 0.f;
#pragma unroll
    for (int ch = 0; ch < NCHUNK; ch++) {
        float4 v = g_chA[ch][c];
        g_hin[ch][c] = make_float2(hr, hi);
        float nr = v.x*hr - v.y*hi + v.z;
        float ni = v.x*hi + v.y*hr + v.w;
        hr = nr; hi = ni;
    }
}

__global__ __launch_bounds__(256) void scan_final(
    const float* __restrict__ A_log, const float* __restrict__ A_imag,
    const float* __restrict__ Dp)
{
    int blk = blockIdx.x;
    int chunk = blk >> 7;
    int rest = blk & 127;
    int bh = rest >> 3, sub = rest & 7;
    int b = bh >> 3, h = bh & 7;
    int tid = threadIdx.x, warp = tid >> 5, lane = tid & 31;
    int n = lane & 15;
    int hd = sub*16 + warp*2 + (lane >> 4);

    float Are2 = -__expf(A_log[h*DS+n]) * LOG2E;
    float Aim = A_imag[h*DS+n];
    float Dv  = Dp[h*HDIM + hd];
    const int ccol = h*HDIM + hd;
    int l0 = chunk * CLEN;
    int row0 = b * LSEQ + l0;
    const size_t zrow = (size_t)b * LSEQ * (2*DI);

    size_t bci = (size_t)row0 * (NH*DS) + h*DS + n;
    size_t dxi = (size_t)row0 * DI + ccol;

    float Bxpr = 0.f, Bxpi = 0.f;
    if (l0 > 0) {
        float4 bc0 = g_bc[bci - NH*DS];
        float4 dx0 = g_dx[dxi - DI];
        Bxpr = dx0.y * bc0.x; Bxpi = dx0.y * bc0.y;
    }
    int c = bh*2048 + sub*256 + tid;
    float2 h0 = g_hin[chunk][c];
    float hr = h0.x, hi = h0.y;

    for (int l = l0; l < l0 + CLEN; l++) {
        float4 bc = g_bc[bci]; bci += NH*DS;
        float4 dx = g_dx[dxi];
        scan_step(Are2, Aim, bc, dx, Bxpr, Bxpi, hr, hi);

        float yv = hr*bc.z + hi*bc.w;
        yv += __shfl_xor_sync(0xffffffffu, yv, 1);
        yv += __shfl_xor_sync(0xffffffffu, yv, 2);
        yv += __shfl_xor_sync(0xffffffffu, yv, 4);
        yv += __shfl_xor_sync(0xffffffffu, yv, 8);

        if (n == 0) {
            float zv = g_xz[zrow + (size_t)l * (2*DI) + DI + ccol];
            float yt = yv + Dv * dx.y;
            float sz = zv / (1.f + __expf(-zv));
            g_ygh[dxi] = __float2half(yt * sz);
        }
        dxi += DI;
    }
}

// ---------------- launch ----------------
extern "C" void kernel_launch(void* const* d_in, const int* in_sizes, int n_in,
                              void* d_out, int out_size)
{
    const float* x          = (const float*)d_in[0];
    const float* in_proj_w  = (const float*)d_in[1];
    const float* conv_w     = (const float*)d_in[2];
    const float* conv_b     = (const float*)d_in[3];
    const float* x_proj_w   = (const float*)d_in[4];
    const float* dt_proj_w  = (const float*)d_in[5];
    const float* dt_proj_b  = (const float*)d_in[6];
    const float* A_log      = (const float*)d_in[7];
    const float* A_imag     = (const float*)d_in[8];
    const float* Dp         = (const float*)d_in[9];
    const float* out_proj_w = (const float*)d_in[10];
    float* out = (float*)d_out;

    float *xz, *proj;
    cudaGetSymbolAddress((void**)&xz,   g_xz);
    cudaGetSymbolAddress((void**)&proj, g_proj);
    __half *xh, *w1h, *xch, *w2h, *ygh, *w3h;
    cudaGetSymbolAddress((void**)&xh,  g_xh);
    cudaGetSymbolAddress((void**)&w1h, g_w1h);
    cudaGetSymbolAddress((void**)&xch, g_xch);
    cudaGetSymbolAddress((void**)&w2h, g_w2h);
    cudaGetSymbolAddress((void**)&ygh, g_ygh);
    cudaGetSymbolAddress((void**)&w3h, g_w3h);

    const int smem128 = (128 + 128) * 144 * 2;   // 73728
    cudaFuncSetAttribute((void*)hmma_gemm<128,1>, cudaFuncAttributeMaxDynamicSharedMemorySize, smem128);
    cudaFuncSetAttribute((void*)hmma_gemm<128,2>, cudaFuncAttributeMaxDynamicSharedMemorySize, smem128);

    // 0) fp16 converts + zero split-K targets (proj, out)
    split_all_kernel<<<(SPTOT + ZTOT + 255)/256, 256>>>(x, in_proj_w, x_proj_w, out_proj_w,
                                                        proj, out);
    // 1) xz = x @ in_proj_w^T   (2048 x 2048, K=512) -> 256 blocks
    hmma_gemm<128,1><<<dim3(16,16), 256, smem128>>>(xh, w1h, xz, 2*DI, 2*DI, DMODEL);
    // 2) xc = silu(conv3(xp)+b)  (+ fp16 convert)
    conv_silu_kernel<<<(MROWS*DI/4 + 255)/256, 256>>>(conv_w, conv_b);
    // 3) proj = xc @ x_proj_w^T (2048 x 560, K=1024), split-K=2 -> 160 blocks
    hmma_gemm<128,2><<<dim3(ODIMP/128,16,2), 256, smem128>>>(xch, w2h, proj, ODIM, ODIM, DI);
    // 4a) repack B/C/gates (must precede sgemm_sp: it reads g_ge)
    repack_kernel<<<(MROWS*NH*DS + 255)/256, 256>>>();
    // 4b) delta = softplus(...) -> packs {delta, xc, bd, gm}
    sgemm_sp<<<dim3(8,16), 256>>>(proj, ODIM, dt_proj_w, DTR, dt_proj_b, DTR);
    // 5) chunked complex scan (R13 core)
    scan_partial<<<NCHUNK*128, 256>>>(A_log, A_imag);
    scan_combine<<<NCHAN/256, 256>>>();
    scan_final<<<NCHUNK*128, 256>>>(A_log, A_imag, Dp);
    // 6) out = yg @ out_proj_w^T (2048 x 512, K=1024), split-K=2 -> 128 blocks
    hmma_gemm<128,2><<<dim3(4,16,2), 256, smem128>>>(ygh, w3h, out, DMODEL, DMODEL, DI);
}